// round 16
// baseline (speedup 1.0000x reference)
#include <cuda_runtime.h>
#include <cuda_fp16.h>
#include <cstdint>
#include <math.h>

// ---------------- problem constants ----------------
#define NB   4
#define CD   512
#define HW   4096
#define TC   1536
#define NGRP 32
#define GSIZE (16*HW)

// ---------------- device scratch (allocation-free) ----------------
__device__ __half g_seq_h[(size_t)NB*HW*CD];
__device__ __half g_qkv_h[(size_t)NB*HW*TC];
__device__ float  g_scores[(size_t)NB*HW*HW];
__device__ __half g_attn_h[(size_t)NB*HW*HW];
__device__ __half g_vt_h[(size_t)NB*CD*HW];
__device__ __half g_attnout_h[(size_t)NB*HW*CD];
__device__ float  g_proj[(size_t)NB*HW*CD];
__device__ __half g_win_h[TC*CD];
__device__ __half g_wout_h[CD*CD];
__device__ float  g_mean[NB*NGRP];
__device__ float  g_rstd[NB*NGRP];

// ---------------- helpers ----------------
static __device__ __forceinline__ uint32_t smem_u32(const void* p) {
    uint32_t a;
    asm("{ .reg .u64 t; cvta.to.shared.u64 t, %1; cvt.u32.u64 %0, t; }" : "=r"(a) : "l"(p));
    return a;
}
static __device__ __forceinline__ void mma_f16(float* c, const uint32_t* a, const uint32_t* b) {
    asm volatile(
        "mma.sync.aligned.m16n8k16.row.col.f32.f16.f16.f32 "
        "{%0,%1,%2,%3}, {%4,%5,%6,%7}, {%8,%9}, {%0,%1,%2,%3};"
        : "+f"(c[0]), "+f"(c[1]), "+f"(c[2]), "+f"(c[3])
        : "r"(a[0]), "r"(a[1]), "r"(a[2]), "r"(a[3]), "r"(b[0]), "r"(b[1]));
}
static __device__ __forceinline__ void ldsm4(uint32_t* r, uint32_t addr) {
    asm volatile("ldmatrix.sync.aligned.m8n8.x4.shared.b16 {%0,%1,%2,%3}, [%4];"
                 : "=r"(r[0]), "=r"(r[1]), "=r"(r[2]), "=r"(r[3]) : "r"(addr));
}
static __device__ __forceinline__ void cp_async16(uint32_t smem_addr, const void* gptr) {
    asm volatile("cp.async.cg.shared.global [%0], [%1], 16;" :: "r"(smem_addr), "l"(gptr));
}
static __device__ __forceinline__ void cp_commit() {
    asm volatile("cp.async.commit_group;" ::: "memory");
}
static __device__ __forceinline__ void cp_wait2() {
    asm volatile("cp.async.wait_group 2;" ::: "memory");
}

// SMEM: 4 stages; per stage A + B, each 128 rows x 12 words (8 data + 4 pad).
#define PITCH 12
#define MATW  (128*PITCH)     // 1536 words
#define STW   (2*MATW)        // 3072 words per stage
// total static smem = 4*STW*4 = 49152 bytes

// ---------------- fp16 tensor GEMM: C = alpha * A * B^T (+bias) ----------------
// A: half [M,K] (lda), B: half [N,K] (ldb). C: HALF_OUT ? half : float (ldc).
// M,N mult of 128, K mult of 16, K >= 48. 512 threads, 16 warps 4x4, warp tile
// 32x32 (2 m16 x 4 n8), k16 chunks, cp.async 4-stage ring, double-buffered
// register fragments (LDSM for chunk kc+1 overlaps MMA of chunk kc).
template<bool HAS_BIAS, bool HALF_OUT>
__global__ __launch_bounds__(512, 1)
void mma_gemm(const __half* __restrict__ Ag, int lda, long long sA,
              const __half* __restrict__ Bg, int ldb, long long sB,
              void* __restrict__ Cg, int ldc, long long sC,
              int K, float alpha, const float* __restrict__ bias)
{
    __shared__ uint32_t sm[4*STW];
    const uint32_t smb = smem_u32(sm);

    const int tid  = threadIdx.x;
    const int lane = tid & 31;
    const int wid  = tid >> 5;        // 0..15
    const int wm   = wid >> 2;        // 0..3
    const int wn   = wid & 3;         // 0..3
    const int tq   = lane >> 2;       // 0..7
    const int tr   = lane & 3;        // 0..3

    const __half* A = Ag + (size_t)blockIdx.z * sA + (size_t)(blockIdx.y * 128) * lda;
    const __half* B = Bg + (size_t)blockIdx.z * sB + (size_t)(blockIdx.x * 128) * ldb;

    // ldmatrix per-lane addressing
    const int lrow = ((lane >> 3) & 1) * 8 + (lane & 7);
    const int lkw  = (lane >> 4) * 4;
    uint32_t a_ad[2], b_ad[2];
    #pragma unroll
    for (int mt = 0; mt < 2; mt++)
        a_ad[mt] = smb + (uint32_t)(((wm*32 + mt*16 + lrow) * PITCH + lkw) * 4);
    #pragma unroll
    for (int p = 0; p < 2; p++)
        b_ad[p]  = smb + (uint32_t)(((wn*32 + p*16 + lrow) * PITCH + lkw) * 4) + MATW*4;

    // cp.async staging: one 16B vector per thread per chunk (512 slots)
    const int msel = tid >> 8;          // 0 = A, 1 = B
    const int srow = (tid >> 1) & 127;
    const int sg   = tid & 1;
    const uint32_t s_wo = (uint32_t)((msel * MATW + srow * PITCH + sg * 4) * 4);
    const __half* s_gp = (msel ? (B + (size_t)srow * ldb) : (A + (size_t)srow * lda)) + sg * 8;

    float acc[8][4];
    #pragma unroll
    for (int i = 0; i < 8; i++) { acc[i][0]=0.f; acc[i][1]=0.f; acc[i][2]=0.f; acc[i][3]=0.f; }

    const int nch = K >> 4;

    // prologue: issue stages 0..2
    #pragma unroll
    for (int s = 0; s < 3; s++) {
        cp_async16(smb + (uint32_t)(s * STW * 4) + s_wo, s_gp + s * 16);
        cp_commit();
    }
    cp_wait2();           // stage 0 complete (3 committed, <=2 pending)
    __syncthreads();

    // fragment double buffers
    uint32_t fa[2][2][4], fb[2][4][2];

    // load fragments for chunk 0 from stage 0
    #pragma unroll
    for (int mt = 0; mt < 2; mt++) ldsm4(fa[0][mt], a_ad[mt]);
    #pragma unroll
    for (int p = 0; p < 2; p++) {
        uint32_t r[4];
        ldsm4(r, b_ad[p]);
        fb[0][p*2][0] = r[0]; fb[0][p*2+1][0] = r[1]; fb[0][p*2][1] = r[2]; fb[0][p*2+1][1] = r[3];
    }

    for (int kc = 0; kc < nch; kc++) {
        const int cur = kc & 1;
        if (kc + 1 < nch) {
            // issue stage kc+3 (empty commit keeps group accounting aligned)
            if (kc + 3 < nch)
                cp_async16(smb + (uint32_t)(((kc + 3) & 3) * STW * 4) + s_wo, s_gp + (kc + 3) * 16);
            cp_commit();
            cp_wait2();   // stage kc+1 complete
            __syncthreads();

            // prefetch fragments for chunk kc+1 (overlaps MMAs below)
            const uint32_t nb = (uint32_t)(((kc + 1) & 3) * STW * 4);
            const int nxt = cur ^ 1;
            #pragma unroll
            for (int mt = 0; mt < 2; mt++) ldsm4(fa[nxt][mt], a_ad[mt] + nb);
            #pragma unroll
            for (int p = 0; p < 2; p++) {
                uint32_t r[4];
                ldsm4(r, b_ad[p] + nb);
                fb[nxt][p*2][0] = r[0]; fb[nxt][p*2+1][0] = r[1];
                fb[nxt][p*2][1] = r[2]; fb[nxt][p*2+1][1] = r[3];
            }
        }

        #pragma unroll
        for (int mt = 0; mt < 2; mt++)
            #pragma unroll
            for (int nt = 0; nt < 4; nt++) mma_f16(acc[mt*4+nt], fa[cur][mt], fb[cur][nt]);
    }

    // epilogue
    #pragma unroll
    for (int mt = 0; mt < 2; mt++) {
        int row0 = blockIdx.y * 128 + wm * 32 + mt * 16 + tq;
        #pragma unroll
        for (int nt = 0; nt < 4; nt++) {
            int col = blockIdx.x * 128 + wn * 32 + nt * 8 + tr * 2;
            float b0 = 0.f, b1 = 0.f;
            if (HAS_BIAS) { b0 = bias[col]; b1 = bias[col + 1]; }
            float v00 = acc[mt*4+nt][0] * alpha + b0, v01 = acc[mt*4+nt][1] * alpha + b1;
            float v10 = acc[mt*4+nt][2] * alpha + b0, v11 = acc[mt*4+nt][3] * alpha + b1;
            if (HALF_OUT) {
                __half* C = (__half*)Cg + (size_t)blockIdx.z * sC;
                *reinterpret_cast<__half2*>(C + (size_t)row0 * ldc + col)       = __floats2half2_rn(v00, v01);
                *reinterpret_cast<__half2*>(C + (size_t)(row0 + 8) * ldc + col) = __floats2half2_rn(v10, v11);
            } else {
                float* C = (float*)Cg + (size_t)blockIdx.z * sC;
                *reinterpret_cast<float2*>(C + (size_t)row0 * ldc + col)       = make_float2(v00, v01);
                *reinterpret_cast<float2*>(C + (size_t)(row0 + 8) * ldc + col) = make_float2(v10, v11);
            }
        }
    }
}

// ---------------- weight fp32 -> fp16 ----------------
__global__ void convert_w_kernel(const float* __restrict__ w_in, const float* __restrict__ w_out) {
    int i = blockIdx.x * 256 + threadIdx.x;
    if (i < TC*CD) g_win_h[i]  = __float2half(w_in[i]);
    if (i < CD*CD) g_wout_h[i] = __float2half(w_out[i]);
}

// ---------------- GroupNorm stats ----------------
__global__ void gn_stats_kernel(const float* __restrict__ x) {
    int bg = blockIdx.x;
    const float* p = x + (size_t)bg * GSIZE;
    float s = 0.f, ss = 0.f;
    for (int i = threadIdx.x * 4; i < GSIZE; i += 256 * 4) {
        float4 v = *reinterpret_cast<const float4*>(p + i);
        s  += v.x + v.y + v.z + v.w;
        ss += v.x*v.x + v.y*v.y + v.z*v.z + v.w*v.w;
    }
    __shared__ float rs[256], rq[256];
    rs[threadIdx.x] = s; rq[threadIdx.x] = ss;
    __syncthreads();
    for (int o = 128; o > 0; o >>= 1) {
        if (threadIdx.x < o) { rs[threadIdx.x] += rs[threadIdx.x+o]; rq[threadIdx.x] += rq[threadIdx.x+o]; }
        __syncthreads();
    }
    if (threadIdx.x == 0) {
        float m   = rs[0] * (1.0f / GSIZE);
        float var = rq[0] * (1.0f / GSIZE) - m * m;
        g_mean[bg] = m;
        g_rstd[bg] = rsqrtf(var + 1e-5f);
    }
}

// ---------------- GroupNorm apply + NCHW -> (n,s,c), half output ----------------
__global__ void gn_apply_kernel(const float* __restrict__ x,
                                const float* __restrict__ gscale,
                                const float* __restrict__ gbias) {
    __shared__ float tile[32][33];
    int n  = blockIdx.z;
    int c0 = blockIdx.y * 32;
    int s0 = blockIdx.x * 32;
    int tx = threadIdx.x, ty = threadIdx.y;
    #pragma unroll
    for (int i = ty; i < 32; i += 8) {
        int c = c0 + i;
        int gidx = n * NGRP + (c >> 4);
        float m = g_mean[gidx], r = g_rstd[gidx];
        float v = x[((size_t)(n * CD + c)) * HW + s0 + tx];
        tile[i][tx] = (v - m) * r * gscale[c] + gbias[c];
    }
    __syncthreads();
    #pragma unroll
    for (int i = ty; i < 32; i += 8)
        g_seq_h[((size_t)(n * HW + s0 + i)) * CD + c0 + tx] = __float2half(tile[tx][i]);
}

// ---------------- V transpose: qkv V part [t,d] half -> g_vt_h [d,t] half ----------------
__global__ void v_transpose_kernel() {
    __shared__ unsigned short tile[32][33];
    int n  = blockIdx.z;
    int d0 = blockIdx.y * 32;
    int t0 = blockIdx.x * 32;
    int tx = threadIdx.x, ty = threadIdx.y;
    #pragma unroll
    for (int i = ty; i < 32; i += 8)
        tile[i][tx] = __half_as_ushort(g_qkv_h[((size_t)(n * HW + t0 + i)) * TC + 1024 + d0 + tx]);
    __syncthreads();
    #pragma unroll
    for (int i = ty; i < 32; i += 8)
        g_vt_h[((size_t)(n * CD + d0 + i)) * HW + t0 + tx] = __ushort_as_half(tile[tx][i]);
}

// ---------------- row softmax: fp32 scores in, half attn out ----------------
__global__ void softmax_kernel() {
    const float* row = g_scores + (size_t)blockIdx.x * HW;
    __half* orow = g_attn_h + (size_t)blockIdx.x * HW;
    int tid = threadIdx.x;
    float4 v[4];
    float mx = -1e30f;
    #pragma unroll
    for (int j = 0; j < 4; j++) {
        v[j] = *reinterpret_cast<const float4*>(row + tid*4 + j*1024);
        mx = fmaxf(mx, fmaxf(fmaxf(v[j].x, v[j].y), fmaxf(v[j].z, v[j].w)));
    }
    __shared__ float red[256];
    red[tid] = mx; __syncthreads();
    for (int o = 128; o > 0; o >>= 1) {
        if (tid < o) red[tid] = fmaxf(red[tid], red[tid+o]);
        __syncthreads();
    }
    mx = red[0];
    __syncthreads();
    float s = 0.f;
    #pragma unroll
    for (int j = 0; j < 4; j++) {
        v[j].x = expf(v[j].x - mx); v[j].y = expf(v[j].y - mx);
        v[j].z = expf(v[j].z - mx); v[j].w = expf(v[j].w - mx);
        s += v[j].x + v[j].y + v[j].z + v[j].w;
    }
    red[tid] = s; __syncthreads();
    for (int o = 128; o > 0; o >>= 1) {
        if (tid < o) red[tid] += red[tid+o];
        __syncthreads();
    }
    float inv = 1.f / red[0];
    #pragma unroll
    for (int j = 0; j < 4; j++) {
        __half2 h01 = __floats2half2_rn(v[j].x * inv, v[j].y * inv);
        __half2 h23 = __floats2half2_rn(v[j].z * inv, v[j].w * inv);
        uint2 u;
        u.x = *reinterpret_cast<uint32_t*>(&h01);
        u.y = *reinterpret_cast<uint32_t*>(&h23);
        *reinterpret_cast<uint2*>(orow + tid*4 + j*1024) = u;
    }
}

// ---------------- (n,s,c) fp32 -> NCHW + residual ----------------
__global__ void out_transpose_kernel(const float* __restrict__ x, float* __restrict__ out) {
    __shared__ float tile[32][33];
    int n  = blockIdx.z;
    int c0 = blockIdx.y * 32;
    int s0 = blockIdx.x * 32;
    int tx = threadIdx.x, ty = threadIdx.y;
    #pragma unroll
    for (int i = ty; i < 32; i += 8)
        tile[i][tx] = g_proj[((size_t)(n * HW + s0 + i)) * CD + c0 + tx];
    __syncthreads();
    #pragma unroll
    for (int i = ty; i < 32; i += 8) {
        size_t idx = ((size_t)(n * CD + c0 + i)) * HW + s0 + tx;
        out[idx] = tile[tx][i] + x[idx];
    }
}

// ---------------- launcher ----------------
extern "C" void kernel_launch(void* const* d_in, const int* in_sizes, int n_in,
                              void* d_out, int out_size) {
    const float* x        = (const float*)d_in[0];
    const float* gn_scale = (const float*)d_in[1];
    const float* gn_bias  = (const float*)d_in[2];
    const float* w_in     = (const float*)d_in[3];
    const float* b_in     = (const float*)d_in[4];
    const float* w_out    = (const float*)d_in[5];
    const float* b_out    = (const float*)d_in[6];
    float* out = (float*)d_out;

    __half *seq_h, *qkv_h, *attn_h, *vt_h, *attnout_h, *win_h, *wout_h;
    float *scores, *proj;
    cudaGetSymbolAddress((void**)&seq_h,     g_seq_h);
    cudaGetSymbolAddress((void**)&qkv_h,     g_qkv_h);
    cudaGetSymbolAddress((void**)&scores,    g_scores);
    cudaGetSymbolAddress((void**)&attn_h,    g_attn_h);
    cudaGetSymbolAddress((void**)&vt_h,      g_vt_h);
    cudaGetSymbolAddress((void**)&attnout_h, g_attnout_h);
    cudaGetSymbolAddress((void**)&proj,      g_proj);
    cudaGetSymbolAddress((void**)&win_h,     g_win_h);
    cudaGetSymbolAddress((void**)&wout_h,    g_wout_h);

    dim3 tb(32, 8);

    // 0) weights -> half
    convert_w_kernel<<<(TC*CD + 255)/256, 256>>>(w_in, w_out);

    // 1) GroupNorm (half output)
    gn_stats_kernel<<<NB * NGRP, 256>>>(x);
    gn_apply_kernel<<<dim3(HW/32, CD/32, NB), tb>>>(x, gn_scale, gn_bias);

    // 2) QKV: seq_h x win_h^T -> qkv_h (half)
    mma_gemm<true, true><<<dim3(TC/128, (NB*HW)/128, 1), 512>>>(
        seq_h, CD, 0LL, win_h, CD, 0LL, qkv_h, TC, 0LL, CD, 1.0f, b_in);

    // 3) scores = Q K^T / sqrt(512) -> fp32
    mma_gemm<false, false><<<dim3(HW/128, HW/128, NB), 512>>>(
        qkv_h, TC, (long long)HW*TC, qkv_h + 512, TC, (long long)HW*TC,
        scores, HW, (long long)HW*HW, CD, 0.044194173824159216f, nullptr);

    // 4) V transpose (half)
    v_transpose_kernel<<<dim3(HW/32, CD/32, NB), tb>>>();

    // 5) softmax -> attn_h (half)
    softmax_kernel<<<NB * HW, 256>>>();

    // 6) attnout = attn * V -> half
    mma_gemm<false, true><<<dim3(CD/128, HW/128, NB), 512>>>(
        attn_h, HW, (long long)HW*HW, vt_h, HW, (long long)CD*HW,
        attnout_h, CD, (long long)HW*CD, HW, 1.0f, nullptr);

    // 7) out-proj -> g_proj (fp32)
    mma_gemm<true, false><<<dim3(CD/128, (NB*HW)/128, 1), 512>>>(
        attnout_h, CD, 0LL, wout_h, CD, 0LL, proj, CD, 0LL, CD, 1.0f, b_out);

    // 8) transpose back + residual
    out_transpose_kernel<<<dim3(HW/32, CD/32, NB), tb>>>(x, out);
}

// round 17
// speedup vs baseline: 1.3284x; 1.3284x over previous
#include <cuda_runtime.h>
#include <cuda_fp16.h>
#include <cstdint>
#include <math.h>

// ---------------- problem constants ----------------
#define NB   4
#define CD   512
#define HW   4096
#define TC   1536
#define NGRP 32
#define GSIZE (16*HW)

// ---------------- device scratch (allocation-free) ----------------
__device__ __half g_seq_h[(size_t)NB*HW*CD];
__device__ __half g_qkv_h[(size_t)NB*HW*TC];
__device__ __half g_scores_h[(size_t)NB*HW*HW];   // raw scores (half, pre-softmax)
__device__ __half g_attn_h[(size_t)NB*HW*HW];
__device__ __half g_vt_h[(size_t)NB*CD*HW];
__device__ __half g_attnout_h[(size_t)NB*HW*CD];
__device__ float  g_proj[(size_t)NB*HW*CD];
__device__ __half g_win_h[TC*CD];
__device__ __half g_wout_h[CD*CD];
__device__ float  g_mean[NB*NGRP];
__device__ float  g_rstd[NB*NGRP];

// ---------------- helpers ----------------
static __device__ __forceinline__ uint32_t smem_u32(const void* p) {
    uint32_t a;
    asm("{ .reg .u64 t; cvta.to.shared.u64 t, %1; cvt.u32.u64 %0, t; }" : "=r"(a) : "l"(p));
    return a;
}
static __device__ __forceinline__ void mma_f16(float* c, const uint32_t* a, const uint32_t* b) {
    asm volatile(
        "mma.sync.aligned.m16n8k16.row.col.f32.f16.f16.f32 "
        "{%0,%1,%2,%3}, {%4,%5,%6,%7}, {%8,%9}, {%0,%1,%2,%3};"
        : "+f"(c[0]), "+f"(c[1]), "+f"(c[2]), "+f"(c[3])
        : "r"(a[0]), "r"(a[1]), "r"(a[2]), "r"(a[3]), "r"(b[0]), "r"(b[1]));
}
static __device__ __forceinline__ void ldsm4(uint32_t* r, uint32_t addr) {
    asm volatile("ldmatrix.sync.aligned.m8n8.x4.shared.b16 {%0,%1,%2,%3}, [%4];"
                 : "=r"(r[0]), "=r"(r[1]), "=r"(r[2]), "=r"(r[3]) : "r"(addr));
}
static __device__ __forceinline__ void cp_async16(uint32_t smem_addr, const void* gptr) {
    asm volatile("cp.async.cg.shared.global [%0], [%1], 16;" :: "r"(smem_addr), "l"(gptr));
}
static __device__ __forceinline__ void cp_commit() {
    asm volatile("cp.async.commit_group;" ::: "memory");
}
static __device__ __forceinline__ void cp_wait1() {
    asm volatile("cp.async.wait_group 1;" ::: "memory");
}
static __device__ __forceinline__ void cp_wait0() {
    asm volatile("cp.async.wait_group 0;" ::: "memory");
}

// SMEM: 4 stages; per stage A + B, each 128 rows x 12 words (8 data + 4 pad).
#define PITCH 12
#define MATW  (128*PITCH)     // 1536 words
#define STW   (2*MATW)        // 3072 words per stage
// total static smem = 4*STW*4 = 49152 bytes

// ---------------- fp16 tensor GEMM: C = alpha * A * B^T (+bias) ----------------
// A: half [M,K] (lda), B: half [N,K] (ldb). C: HALF_OUT ? half : float (ldc).
// M,N mult of 128, K mult of 16. 256 threads, 8 warps 4(M)x2(N), warp tile 32x64
// (2 m16 x 8 n8), k16 chunks, cp.async 4-stage ring.  (R15-proven structure.)
template<bool HAS_BIAS, bool HALF_OUT>
__global__ __launch_bounds__(256, 2)
void mma_gemm(const __half* __restrict__ Ag, int lda, long long sA,
              const __half* __restrict__ Bg, int ldb, long long sB,
              void* __restrict__ Cg, int ldc, long long sC,
              int K, float alpha, const float* __restrict__ bias)
{
    __shared__ uint32_t sm[4*STW];
    const uint32_t smb = smem_u32(sm);

    const int tid  = threadIdx.x;
    const int lane = tid & 31;
    const int wid  = tid >> 5;        // 0..7
    const int wm   = wid >> 1;        // 0..3  (M)
    const int wn   = wid & 1;         // 0..1  (N)
    const int tq   = lane >> 2;       // 0..7
    const int tr   = lane & 3;        // 0..3

    const __half* A = Ag + (size_t)blockIdx.z * sA + (size_t)(blockIdx.y * 128) * lda;
    const __half* B = Bg + (size_t)blockIdx.z * sB + (size_t)(blockIdx.x * 128) * ldb;

    // ldmatrix per-lane addressing
    const int lrow = ((lane >> 3) & 1) * 8 + (lane & 7);
    const int lkw  = (lane >> 4) * 4;
    uint32_t a_ad[2], b_ad[4];
    #pragma unroll
    for (int mt = 0; mt < 2; mt++)
        a_ad[mt] = smb + (uint32_t)(((wm*32 + mt*16 + lrow) * PITCH + lkw) * 4);
    #pragma unroll
    for (int p = 0; p < 4; p++)
        b_ad[p]  = smb + (uint32_t)(((wn*64 + p*16 + lrow) * PITCH + lkw) * 4) + MATW*4;

    // cp.async staging: 2 x 16B per thread per chunk (512 slots: 2 mats x 128 rows x 2 groups)
    uint32_t s_wo[2];
    const __half* s_gp[2];
    #pragma unroll
    for (int s = 0; s < 2; s++) {
        int idx  = tid + s * 256;
        int msel = idx >> 8;           // 0 = A, 1 = B
        int r    = (idx >> 1) & 127;
        int g    = idx & 1;
        s_wo[s] = (uint32_t)(msel * MATW + r * PITCH + g * 4);
        s_gp[s] = (msel ? (B + (size_t)r * ldb) : (A + (size_t)r * lda)) + g * 8;
    }

    float acc[16][4];
    #pragma unroll
    for (int i = 0; i < 16; i++) { acc[i][0]=0.f; acc[i][1]=0.f; acc[i][2]=0.f; acc[i][3]=0.f; }

    const int nch = K >> 4;

    // prologue: stage 0 = chunk 0
    #pragma unroll
    for (int s = 0; s < 2; s++) cp_async16(smb + s_wo[s] * 4, s_gp[s]);
    cp_commit();

    for (int kc = 0; kc < nch; kc++) {
        if (kc + 1 < nch) {
            const uint32_t nst = (uint32_t)(((kc + 1) & 3) * STW * 4);
            #pragma unroll
            for (int s = 0; s < 2; s++) cp_async16(smb + nst + s_wo[s] * 4, s_gp[s] + (kc + 1) * 16);
            cp_commit();
            cp_wait1();
        } else {
            cp_wait0();
        }
        __syncthreads();

        const uint32_t sbase = (uint32_t)((kc & 3) * STW * 4);
        uint32_t ah[2][4], bh[8][2];
        #pragma unroll
        for (int mt = 0; mt < 2; mt++) ldsm4(ah[mt], a_ad[mt] + sbase);
        #pragma unroll
        for (int p = 0; p < 4; p++) {
            uint32_t r[4];
            ldsm4(r, b_ad[p] + sbase);
            bh[p*2][0] = r[0]; bh[p*2+1][0] = r[1]; bh[p*2][1] = r[2]; bh[p*2+1][1] = r[3];
        }

        #pragma unroll
        for (int mt = 0; mt < 2; mt++)
            #pragma unroll
            for (int nt = 0; nt < 8; nt++) mma_f16(acc[mt*8+nt], ah[mt], bh[nt]);
    }

    // epilogue
    #pragma unroll
    for (int mt = 0; mt < 2; mt++) {
        int row0 = blockIdx.y * 128 + wm * 32 + mt * 16 + tq;
        #pragma unroll
        for (int nt = 0; nt < 8; nt++) {
            int col = blockIdx.x * 128 + wn * 64 + nt * 8 + tr * 2;
            float b0 = 0.f, b1 = 0.f;
            if (HAS_BIAS) { b0 = bias[col]; b1 = bias[col + 1]; }
            float v00 = acc[mt*8+nt][0] * alpha + b0, v01 = acc[mt*8+nt][1] * alpha + b1;
            float v10 = acc[mt*8+nt][2] * alpha + b0, v11 = acc[mt*8+nt][3] * alpha + b1;
            if (HALF_OUT) {
                __half* C = (__half*)Cg + (size_t)blockIdx.z * sC;
                *reinterpret_cast<__half2*>(C + (size_t)row0 * ldc + col)       = __floats2half2_rn(v00, v01);
                *reinterpret_cast<__half2*>(C + (size_t)(row0 + 8) * ldc + col) = __floats2half2_rn(v10, v11);
            } else {
                float* C = (float*)Cg + (size_t)blockIdx.z * sC;
                *reinterpret_cast<float2*>(C + (size_t)row0 * ldc + col)       = make_float2(v00, v01);
                *reinterpret_cast<float2*>(C + (size_t)(row0 + 8) * ldc + col) = make_float2(v10, v11);
            }
        }
    }
}

// ---------------- weight fp32 -> fp16 ----------------
__global__ void convert_w_kernel(const float* __restrict__ w_in, const float* __restrict__ w_out) {
    int i = blockIdx.x * 256 + threadIdx.x;
    if (i < TC*CD) g_win_h[i]  = __float2half(w_in[i]);
    if (i < CD*CD) g_wout_h[i] = __float2half(w_out[i]);
}

// ---------------- GroupNorm stats ----------------
__global__ void gn_stats_kernel(const float* __restrict__ x) {
    int bg = blockIdx.x;
    const float* p = x + (size_t)bg * GSIZE;
    float s = 0.f, ss = 0.f;
    for (int i = threadIdx.x * 4; i < GSIZE; i += 256 * 4) {
        float4 v = *reinterpret_cast<const float4*>(p + i);
        s  += v.x + v.y + v.z + v.w;
        ss += v.x*v.x + v.y*v.y + v.z*v.z + v.w*v.w;
    }
    __shared__ float rs[256], rq[256];
    rs[threadIdx.x] = s; rq[threadIdx.x] = ss;
    __syncthreads();
    for (int o = 128; o > 0; o >>= 1) {
        if (threadIdx.x < o) { rs[threadIdx.x] += rs[threadIdx.x+o]; rq[threadIdx.x] += rq[threadIdx.x+o]; }
        __syncthreads();
    }
    if (threadIdx.x == 0) {
        float m   = rs[0] * (1.0f / GSIZE);
        float var = rq[0] * (1.0f / GSIZE) - m * m;
        g_mean[bg] = m;
        g_rstd[bg] = rsqrtf(var + 1e-5f);
    }
}

// ---------------- GroupNorm apply + NCHW -> (n,s,c), half output ----------------
__global__ void gn_apply_kernel(const float* __restrict__ x,
                                const float* __restrict__ gscale,
                                const float* __restrict__ gbias) {
    __shared__ float tile[32][33];
    int n  = blockIdx.z;
    int c0 = blockIdx.y * 32;
    int s0 = blockIdx.x * 32;
    int tx = threadIdx.x, ty = threadIdx.y;
    #pragma unroll
    for (int i = ty; i < 32; i += 8) {
        int c = c0 + i;
        int gidx = n * NGRP + (c >> 4);
        float m = g_mean[gidx], r = g_rstd[gidx];
        float v = x[((size_t)(n * CD + c)) * HW + s0 + tx];
        tile[i][tx] = (v - m) * r * gscale[c] + gbias[c];
    }
    __syncthreads();
    #pragma unroll
    for (int i = ty; i < 32; i += 8)
        g_seq_h[((size_t)(n * HW + s0 + i)) * CD + c0 + tx] = __float2half(tile[tx][i]);
}

// ---------------- V transpose: qkv V part [t,d] half -> g_vt_h [d,t] half ----------------
__global__ void v_transpose_kernel() {
    __shared__ unsigned short tile[32][33];
    int n  = blockIdx.z;
    int d0 = blockIdx.y * 32;
    int t0 = blockIdx.x * 32;
    int tx = threadIdx.x, ty = threadIdx.y;
    #pragma unroll
    for (int i = ty; i < 32; i += 8)
        tile[i][tx] = __half_as_ushort(g_qkv_h[((size_t)(n * HW + t0 + i)) * TC + 1024 + d0 + tx]);
    __syncthreads();
    #pragma unroll
    for (int i = ty; i < 32; i += 8)
        g_vt_h[((size_t)(n * CD + d0 + i)) * HW + t0 + tx] = __ushort_as_half(tile[tx][i]);
}

// ---------------- row softmax: half scores in, half attn out ----------------
__global__ void softmax_kernel() {
    const uint4* row = reinterpret_cast<const uint4*>(g_scores_h + (size_t)blockIdx.x * HW);
    uint4* orow = reinterpret_cast<uint4*>(g_attn_h + (size_t)blockIdx.x * HW);
    int tid = threadIdx.x;

    // 2 x uint4 = 16 halfs per thread
    uint4 u[2];
    float f[16];
    #pragma unroll
    for (int j = 0; j < 2; j++) u[j] = row[tid + j * 256];
    #pragma unroll
    for (int j = 0; j < 2; j++) {
        const __half2* h2 = reinterpret_cast<const __half2*>(&u[j]);
        #pragma unroll
        for (int q = 0; q < 4; q++) {
            float2 fv = __half22float2(h2[q]);
            f[j*8 + q*2]     = fv.x;
            f[j*8 + q*2 + 1] = fv.y;
        }
    }

    float mx = -1e30f;
    #pragma unroll
    for (int i = 0; i < 16; i++) mx = fmaxf(mx, f[i]);
    __shared__ float red[256];
    red[tid] = mx; __syncthreads();
    for (int o = 128; o > 0; o >>= 1) {
        if (tid < o) red[tid] = fmaxf(red[tid], red[tid+o]);
        __syncthreads();
    }
    mx = red[0];
    __syncthreads();

    float s = 0.f;
    #pragma unroll
    for (int i = 0; i < 16; i++) { f[i] = expf(f[i] - mx); s += f[i]; }
    red[tid] = s; __syncthreads();
    for (int o = 128; o > 0; o >>= 1) {
        if (tid < o) red[tid] += red[tid+o];
        __syncthreads();
    }
    float inv = 1.f / red[0];

    #pragma unroll
    for (int j = 0; j < 2; j++) {
        uint4 w;
        __half2* h2 = reinterpret_cast<__half2*>(&w);
        #pragma unroll
        for (int q = 0; q < 4; q++)
            h2[q] = __floats2half2_rn(f[j*8 + q*2] * inv, f[j*8 + q*2 + 1] * inv);
        orow[tid + j * 256] = w;
    }
}

// ---------------- (n,s,c) fp32 -> NCHW + residual ----------------
__global__ void out_transpose_kernel(const float* __restrict__ x, float* __restrict__ out) {
    __shared__ float tile[32][33];
    int n  = blockIdx.z;
    int c0 = blockIdx.y * 32;
    int s0 = blockIdx.x * 32;
    int tx = threadIdx.x, ty = threadIdx.y;
    #pragma unroll
    for (int i = ty; i < 32; i += 8)
        tile[i][tx] = g_proj[((size_t)(n * HW + s0 + i)) * CD + c0 + tx];
    __syncthreads();
    #pragma unroll
    for (int i = ty; i < 32; i += 8) {
        size_t idx = ((size_t)(n * CD + c0 + i)) * HW + s0 + tx;
        out[idx] = tile[tx][i] + x[idx];
    }
}

// ---------------- launcher ----------------
extern "C" void kernel_launch(void* const* d_in, const int* in_sizes, int n_in,
                              void* d_out, int out_size) {
    const float* x        = (const float*)d_in[0];
    const float* gn_scale = (const float*)d_in[1];
    const float* gn_bias  = (const float*)d_in[2];
    const float* w_in     = (const float*)d_in[3];
    const float* b_in     = (const float*)d_in[4];
    const float* w_out    = (const float*)d_in[5];
    const float* b_out    = (const float*)d_in[6];
    float* out = (float*)d_out;

    __half *seq_h, *qkv_h, *scores_h, *attn_h, *vt_h, *attnout_h, *win_h, *wout_h;
    float *proj;
    cudaGetSymbolAddress((void**)&seq_h,     g_seq_h);
    cudaGetSymbolAddress((void**)&qkv_h,     g_qkv_h);
    cudaGetSymbolAddress((void**)&scores_h,  g_scores_h);
    cudaGetSymbolAddress((void**)&attn_h,    g_attn_h);
    cudaGetSymbolAddress((void**)&vt_h,      g_vt_h);
    cudaGetSymbolAddress((void**)&attnout_h, g_attnout_h);
    cudaGetSymbolAddress((void**)&proj,      g_proj);
    cudaGetSymbolAddress((void**)&win_h,     g_win_h);
    cudaGetSymbolAddress((void**)&wout_h,    g_wout_h);

    dim3 tb(32, 8);

    // 0) weights -> half
    convert_w_kernel<<<(TC*CD + 255)/256, 256>>>(w_in, w_out);

    // 1) GroupNorm (half output)
    gn_stats_kernel<<<NB * NGRP, 256>>>(x);
    gn_apply_kernel<<<dim3(HW/32, CD/32, NB), tb>>>(x, gn_scale, gn_bias);

    // 2) QKV: seq_h x win_h^T -> qkv_h (half)
    mma_gemm<true, true><<<dim3(TC/128, (NB*HW)/128, 1), 256>>>(
        seq_h, CD, 0LL, win_h, CD, 0LL, qkv_h, TC, 0LL, CD, 1.0f, b_in);

    // 3) scores = Q K^T / sqrt(512) -> half
    mma_gemm<false, true><<<dim3(HW/128, HW/128, NB), 256>>>(
        qkv_h, TC, (long long)HW*TC, qkv_h + 512, TC, (long long)HW*TC,
        scores_h, HW, (long long)HW*HW, CD, 0.044194173824159216f, nullptr);

    // 4) V transpose (half)
    v_transpose_kernel<<<dim3(HW/32, CD/32, NB), tb>>>();

    // 5) softmax (half in) -> attn_h (half)
    softmax_kernel<<<NB * HW, 256>>>();

    // 6) attnout = attn * V -> half
    mma_gemm<false, true><<<dim3(CD/128, HW/128, NB), 256>>>(
        attn_h, HW, (long long)HW*HW, vt_h, HW, (long long)CD*HW,
        attnout_h, CD, (long long)HW*CD, HW, 1.0f, nullptr);

    // 7) out-proj -> g_proj (fp32)
    mma_gemm<true, false><<<dim3(CD/128, (NB*HW)/128, 1), 256>>>(
        attnout_h, CD, 0LL, wout_h, CD, 0LL, proj, CD, 0LL, CD, 1.0f, b_out);

    // 8) transpose back + residual
    out_transpose_kernel<<<dim3(HW/32, CD/32, NB), tb>>>(x, out);
}